// round 5
// baseline (speedup 1.0000x reference)
#include <cuda_runtime.h>
#include <cuda_bf16.h>

#define NN   4096
#define TT   48
#define HH   64
#define C4   256
#define MAXW 128
#define ROWS 16

typedef unsigned long long ull;

// ---------------- device scratch (no allocations allowed) ----------------
__device__ __align__(16) float g_dinv[NN];
__device__ __align__(16) int   g_cols[NN * MAXW];
__device__ __align__(16) float g_vals[NN * MAXW];
__device__ __align__(16) int   g_len[NN];
__device__ __align__(16) float g_AX[TT * NN * 2];
__device__ __align__(16) float g_W0[128 * C4];   // [gcWh0 ; liWh0]
__device__ __align__(16) float g_Wx0[4 * C4];    // [gcWi0 ; liWi0]
__device__ __align__(16) float g_b0[C4];
__device__ __align__(16) float g_W1[256 * C4];   // [gcWi1 ; liWi1 ; gcWh1 ; liWh1]
__device__ __align__(16) float g_b1[C4];
__device__ __align__(16) float g_h0[2][NN * HH];
__device__ __align__(16) float g_c0[2][NN * HH];
__device__ __align__(16) float g_h1[2][NN * HH];
__device__ __align__(16) float g_c1[2][NN * HH];

// ---------------- helpers ----------------
__device__ __forceinline__ ull pack2(float x, float y) {
    ull r; asm("mov.b64 %0,{%1,%2};" : "=l"(r) : "f"(x), "f"(y)); return r;
}
__device__ __forceinline__ void unpack2(ull v, float& x, float& y) {
    asm("mov.b64 {%0,%1},%2;" : "=f"(x), "=f"(y) : "l"(v));
}
// Blackwell packed dual-FMA (2x fp32 throughput); PTX-only form
__device__ __forceinline__ void fma2(ull& d, ull a, ull b) {
    asm("fma.rn.f32x2 %0,%1,%2,%0;" : "+l"(d) : "l"(a), "l"(b));
}
__device__ __forceinline__ float sigf(float v)  { return 1.f / (1.f + __expf(-v)); }
__device__ __forceinline__ float tanhf2(float v){ return 2.f / (1.f + __expf(-2.f * v)) - 1.f; }

// ---------------- setup kernels ----------------
__global__ void k_dinv(const float* __restrict__ adj) {
    int row  = blockIdx.x * 8 + (threadIdx.x >> 5);
    int lane = threadIdx.x & 31;
    if (row >= NN) return;
    float s = 0.f;
    for (int j = lane; j < NN; j += 32) s += adj[(size_t)row * NN + j];
    #pragma unroll
    for (int o = 16; o; o >>= 1) s += __shfl_xor_sync(0xffffffffu, s, o);
    if (lane == 0) g_dinv[row] = rsqrtf(s + 1.f);   // A = adj + I
}

__global__ void k_build(const float* __restrict__ adj) {
    int row  = blockIdx.x * 8 + (threadIdx.x >> 5);
    int lane = threadIdx.x & 31;
    if (row >= NN) return;
    float dr = g_dinv[row];
    int base = 0;
    for (int j0 = 0; j0 < NN; j0 += 32) {
        int   j    = j0 + lane;
        float v    = adj[(size_t)row * NN + j];
        bool  pres = (v != 0.f) || (j == row);
        float aval = v + ((j == row) ? 1.f : 0.f);
        unsigned m = __ballot_sync(0xffffffffu, pres);
        if (pres) {
            int pos = base + __popc(m & ((1u << lane) - 1u));
            if (pos < MAXW) {
                g_cols[row * MAXW + pos] = j;
                g_vals[row * MAXW + pos] = aval * dr * g_dinv[j];
            }
        }
        base += __popc(m);
    }
    if (base > MAXW) base = MAXW;
    if (lane == 0) g_len[row] = base;
}

__global__ void k_pack(const float* gcWi0, const float* gcWh0, const float* liWi0, const float* liWh0,
                       const float* gcWi1, const float* liWi1, const float* gcWh1, const float* liWh1,
                       const float* bi0, const float* bh0, const float* lbi0, const float* lbh0,
                       const float* bi1, const float* bh1, const float* lbi1, const float* lbh1) {
    int idx = blockIdx.x * blockDim.x + threadIdx.x;
    const int W0E = 128 * C4, W1E = 256 * C4, WXE = 4 * C4;
    if (idx < W0E) {
        int r = idx >> 8, c = idx & 255;
        g_W0[idx] = (r < 64) ? gcWh0[r * C4 + c] : liWh0[(r - 64) * C4 + c];
    } else if (idx < W0E + W1E) {
        int j = idx - W0E; int r = j >> 8, c = j & 255;
        int seg = r >> 6, rr = r & 63;
        const float* s = (seg == 0) ? gcWi1 : (seg == 1) ? liWi1 : (seg == 2) ? gcWh1 : liWh1;
        g_W1[j] = s[rr * C4 + c];
    } else if (idx < W0E + W1E + WXE) {
        int j = idx - W0E - W1E; int q = j >> 8, c = j & 255;
        g_Wx0[j] = (q < 2) ? gcWi0[q * C4 + c] : liWi0[(q - 2) * C4 + c];
    } else if (idx < W0E + W1E + WXE + C4) {
        int c = idx - (W0E + W1E + WXE);
        g_b0[c] = bi0[c] + bh0[c] + lbi0[c] + lbh0[c];
    } else if (idx < W0E + W1E + WXE + 2 * C4) {
        int c = idx - (W0E + W1E + WXE + C4);
        g_b1[c] = bi1[c] + bh1[c] + lbi1[c] + lbh1[c];
    }
}

__global__ void k_ax(const float* __restrict__ x) {
    int idx = blockIdx.x * blockDim.x + threadIdx.x;
    if (idx >= TT * NN) return;
    int t = idx / NN, i = idx - t * NN;
    int len = g_len[i];
    const int*   cp = g_cols + (size_t)i * MAXW;
    const float* vp = g_vals + (size_t)i * MAXW;
    float a0 = 0.f, a1 = 0.f;
    for (int k = 0; k < len; k++) {
        int c = cp[k]; float v = vp[k];
        float2 xv = *(const float2*)&x[(size_t)t * (NN * 2) + c * 2];
        a0 += v * xv.x; a1 += v * xv.y;
    }
    *(float2*)&g_AX[((size_t)t * NN + i) * 2] = make_float2(a0, a1);
}

__global__ void k_zero() {
    int idx = blockIdx.x * blockDim.x + threadIdx.x;
    if (idx < NN * HH) {
        g_h0[0][idx] = 0.f; g_c0[0][idx] = 0.f;
        g_h1[0][idx] = 0.f; g_c1[0][idx] = 0.f;
    }
}

// ---------------- cell 0: Ah0 gather + [Ah0|h0]@W0 + [AX|x]@Wx0 + gates ----------------
__global__ __launch_bounds__(256) void k_cell0(const float* __restrict__ x, int t, int pin, int pout) {
    __shared__ __align__(16) float su[ROWS][128];
    __shared__ __align__(16) float sW[16][C4];
    __shared__ __align__(16) float sWx[4][C4];
    __shared__ __align__(16) float sx[ROWS][4];
    const int tid  = threadIdx.x;
    const int row0 = blockIdx.x * ROWS;
    const float* __restrict__ h0o = g_h0[pin];

    // stage h0_old rows -> su[:,64:128)
    {
        int r = tid >> 4, q = tid & 15;
        *(float4*)&su[r][64 + q * 4] = *(const float4*)&h0o[(size_t)(row0 + r) * HH + q * 4];
    }
    // stage sWx (4x256)
    {
        int kk = tid >> 6, q = tid & 63;
        *(float4*)&sWx[kk][q * 4] = *(const float4*)&g_Wx0[kk * C4 + q * 4];
    }
    // stage x-term inputs
    if (tid < ROWS) {
        float2 axv = *(const float2*)&g_AX[((size_t)t * NN + row0 + tid) * 2];
        float2 xv  = *(const float2*)&x[(size_t)t * (NN * 2) + (row0 + tid) * 2];
        sx[tid][0] = axv.x; sx[tid][1] = axv.y;
        sx[tid][2] = xv.x;  sx[tid][3] = xv.y;
    }
    // gather (A @ h0_old) -> su[:,0:64)
    {
        const int row = tid >> 4, lane = tid & 15;
        const int grow = row0 + row;
        const int len = g_len[grow];
        const int*   cb = g_cols + (size_t)grow * MAXW;
        const float* vb = g_vals + (size_t)grow * MAXW;
        float4 acc = make_float4(0.f, 0.f, 0.f, 0.f);
        #pragma unroll 4
        for (int k = 0; k < len; k++) {
            int c = cb[k]; float v = vb[k];
            float4 hv = *(const float4*)&h0o[(size_t)c * HH + lane * 4];
            acc.x += v * hv.x; acc.y += v * hv.y; acc.z += v * hv.z; acc.w += v * hv.w;
        }
        *(float4*)&su[row][lane * 4] = acc;
    }
    __syncthreads();

    // GEMM: [16 x 128] @ [128 x 256]; thread = 4 rows x 4 cols
    const int cg = tid & 63, rg = tid >> 6;
    const int c0 = cg * 4, r0 = rg * 4;
    ull acc[4][2];
    {
        float4 bb = *(const float4*)&g_b0[c0];
        ull b01 = pack2(bb.x, bb.y), b23 = pack2(bb.z, bb.w);
        #pragma unroll
        for (int r = 0; r < 4; r++) { acc[r][0] = b01; acc[r][1] = b23; }
        // x-term (K = 4)
        #pragma unroll
        for (int q = 0; q < 4; q++) {
            ull w0 = *(const ull*)&sWx[q][c0];
            ull w1 = *(const ull*)&sWx[q][c0 + 2];
            #pragma unroll
            for (int r = 0; r < 4; r++) {
                float uv = sx[r0 + r][q];
                ull uu = pack2(uv, uv);
                fma2(acc[r][0], uu, w0); fma2(acc[r][1], uu, w1);
            }
        }
    }
    for (int kt = 0; kt < 8; kt++) {
        // load W0 tile [16 x 256]
        {
            int i0 = tid;           // 1024 float4 slots / 256 threads = 4
            #pragma unroll
            for (int it = 0; it < 4; it++) {
                int i = i0 + it * 256;
                int kk = i >> 6, q = i & 63;
                *(float4*)&sW[kk][q * 4] = *(const float4*)&g_W0[(size_t)(kt * 16 + kk) * C4 + q * 4];
            }
        }
        __syncthreads();
        #pragma unroll
        for (int kk = 0; kk < 16; kk++) {
            int k = kt * 16 + kk;
            ull w0 = *(const ull*)&sW[kk][c0];
            ull w1 = *(const ull*)&sW[kk][c0 + 2];
            #pragma unroll
            for (int r = 0; r < 4; r++) {
                float uv = su[r0 + r][k];
                ull uu = pack2(uv, uv);
                fma2(acc[r][0], uu, w0); fma2(acc[r][1], uu, w1);
            }
        }
        __syncthreads();
    }

    // write comb into sW (reuse as [16][256]) then gates
    #pragma unroll
    for (int r = 0; r < 4; r++) {
        float a, b;
        unpack2(acc[r][0], a, b); *(float2*)&sW[r0 + r][c0]     = make_float2(a, b);
        unpack2(acc[r][1], a, b); *(float2*)&sW[r0 + r][c0 + 2] = make_float2(a, b);
    }
    __syncthreads();

    const float* __restrict__ cold = g_c0[pin];
    float* __restrict__ hn = g_h0[pout];
    float* __restrict__ cn = g_c0[pout];
    #pragma unroll
    for (int it = 0; it < 4; it++) {
        int i = tid + it * 256;               // 16*64 = 1024 slots
        int r = i >> 6, h = i & 63;
        float ig = sW[r][h], fg = sW[r][64 + h], og = sW[r][128 + h], gg = sW[r][192 + h];
        size_t gi = (size_t)(row0 + r) * HH + h;
        float cv = sigf(fg) * cold[gi] + sigf(ig) * tanhf2(gg);
        cn[gi] = cv;
        hn[gi] = sigf(og) * tanhf2(cv);
    }
}

// ---------------- cell 1: Ah0,Ah1 gathers + [Ah0|h0|Ah1|h1]@W1 + gates ----------------
__global__ __launch_bounds__(256) void k_cell1(int pin, int pout) {
    __shared__ __align__(16) float su[ROWS][C4];
    __shared__ __align__(16) float sW[16][C4];
    const int tid  = threadIdx.x;
    const int row0 = blockIdx.x * ROWS;
    const float* __restrict__ h0n = g_h0[pout];   // new h0 from cell0 this step
    const float* __restrict__ h1o = g_h1[pin];

    // stage h0n -> su[:,64:128), h1o -> su[:,192:256)
    {
        int r = tid >> 4, q = tid & 15;
        *(float4*)&su[r][64  + q * 4] = *(const float4*)&h0n[(size_t)(row0 + r) * HH + q * 4];
        *(float4*)&su[r][192 + q * 4] = *(const float4*)&h1o[(size_t)(row0 + r) * HH + q * 4];
    }
    // gather A@h0n -> su[:,0:64), A@h1o -> su[:,128:192)
    {
        const int row = tid >> 4, lane = tid & 15;
        const int grow = row0 + row;
        const int len = g_len[grow];
        const int*   cb = g_cols + (size_t)grow * MAXW;
        const float* vb = g_vals + (size_t)grow * MAXW;
        float4 a0 = make_float4(0.f, 0.f, 0.f, 0.f);
        float4 a1 = make_float4(0.f, 0.f, 0.f, 0.f);
        #pragma unroll 2
        for (int k = 0; k < len; k++) {
            int c = cb[k]; float v = vb[k];
            float4 hv0 = *(const float4*)&h0n[(size_t)c * HH + lane * 4];
            float4 hv1 = *(const float4*)&h1o[(size_t)c * HH + lane * 4];
            a0.x += v * hv0.x; a0.y += v * hv0.y; a0.z += v * hv0.z; a0.w += v * hv0.w;
            a1.x += v * hv1.x; a1.y += v * hv1.y; a1.z += v * hv1.z; a1.w += v * hv1.w;
        }
        *(float4*)&su[row][lane * 4]       = a0;
        *(float4*)&su[row][128 + lane * 4] = a1;
    }
    __syncthreads();

    // GEMM: [16 x 256] @ [256 x 256]
    const int cg = tid & 63, rg = tid >> 6;
    const int c0 = cg * 4, r0 = rg * 4;
    ull acc[4][2];
    {
        float4 bb = *(const float4*)&g_b1[c0];
        ull b01 = pack2(bb.x, bb.y), b23 = pack2(bb.z, bb.w);
        #pragma unroll
        for (int r = 0; r < 4; r++) { acc[r][0] = b01; acc[r][1] = b23; }
    }
    for (int kt = 0; kt < 16; kt++) {
        {
            int i0 = tid;
            #pragma unroll
            for (int it = 0; it < 4; it++) {
                int i = i0 + it * 256;
                int kk = i >> 6, q = i & 63;
                *(float4*)&sW[kk][q * 4] = *(const float4*)&g_W1[(size_t)(kt * 16 + kk) * C4 + q * 4];
            }
        }
        __syncthreads();
        #pragma unroll
        for (int kk = 0; kk < 16; kk++) {
            int k = kt * 16 + kk;
            ull w0 = *(const ull*)&sW[kk][c0];
            ull w1 = *(const ull*)&sW[kk][c0 + 2];
            #pragma unroll
            for (int r = 0; r < 4; r++) {
                float uv = su[r0 + r][k];
                ull uu = pack2(uv, uv);
                fma2(acc[r][0], uu, w0); fma2(acc[r][1], uu, w1);
            }
        }
        __syncthreads();
    }

    // write comb into su (reuse), then gates
    #pragma unroll
    for (int r = 0; r < 4; r++) {
        float a, b;
        unpack2(acc[r][0], a, b); *(float2*)&su[r0 + r][c0]     = make_float2(a, b);
        unpack2(acc[r][1], a, b); *(float2*)&su[r0 + r][c0 + 2] = make_float2(a, b);
    }
    __syncthreads();

    const float* __restrict__ cold = g_c1[pin];
    float* __restrict__ hn = g_h1[pout];
    float* __restrict__ cn = g_c1[pout];
    #pragma unroll
    for (int it = 0; it < 4; it++) {
        int i = tid + it * 256;
        int r = i >> 6, h = i & 63;
        float ig = su[r][h], fg = su[r][64 + h], og = su[r][128 + h], gg = su[r][192 + h];
        size_t gi = (size_t)(row0 + r) * HH + h;
        float cv = sigf(fg) * cold[gi] + sigf(ig) * tanhf2(gg);
        cn[gi] = cv;
        hn[gi] = sigf(og) * tanhf2(cv);
    }
}

// ---------------- output projection: h1 @ outW + outb ----------------
__global__ void k_out(const float* __restrict__ outW, const float* __restrict__ outb,
                      float* __restrict__ out, int hbuf) {
    int idx = blockIdx.x * blockDim.x + threadIdx.x;
    if (idx >= NN * 12) return;
    int n = idx / 12, p = idx - n * 12;
    const float* h = g_h1[hbuf] + (size_t)n * HH;
    float s = outb[p];
    #pragma unroll
    for (int k = 0; k < HH; k++) s += h[k] * outW[k * 12 + p];
    out[idx] = s;
}

extern "C" void kernel_launch(void* const* d_in, const int* in_sizes, int n_in,
                              void* d_out, int out_size) {
    const float* x     = (const float*)d_in[0];
    const float* adj   = (const float*)d_in[1];
    const float* gcWi0 = (const float*)d_in[2];
    const float* gcbi0 = (const float*)d_in[3];
    const float* gcWh0 = (const float*)d_in[4];
    const float* gcbh0 = (const float*)d_in[5];
    const float* liWi0 = (const float*)d_in[6];
    const float* libi0 = (const float*)d_in[7];
    const float* liWh0 = (const float*)d_in[8];
    const float* libh0 = (const float*)d_in[9];
    const float* gcWi1 = (const float*)d_in[10];
    const float* gcbi1 = (const float*)d_in[11];
    const float* gcWh1 = (const float*)d_in[12];
    const float* gcbh1 = (const float*)d_in[13];
    const float* liWi1 = (const float*)d_in[14];
    const float* libi1 = (const float*)d_in[15];
    const float* liWh1 = (const float*)d_in[16];
    const float* libh1 = (const float*)d_in[17];
    const float* outW  = (const float*)d_in[18];
    const float* outb  = (const float*)d_in[19];
    float* out = (float*)d_out;

    k_dinv<<<NN / 8, 256>>>(adj);
    k_build<<<NN / 8, 256>>>(adj);
    k_pack<<<(128 * C4 + 256 * C4 + 4 * C4 + 2 * C4 + 255) / 256, 256>>>(
        gcWi0, gcWh0, liWi0, liWh0, gcWi1, liWi1, gcWh1, liWh1,
        gcbi0, gcbh0, libi0, libh0, gcbi1, gcbh1, libi1, libh1);
    k_zero<<<(NN * HH + 255) / 256, 256>>>();
    k_ax<<<(TT * NN + 255) / 256, 256>>>(x);

    for (int t = 0; t < TT; t++) {
        int pin = t & 1, pout = pin ^ 1;
        k_cell0<<<NN / ROWS, 256>>>(x, t, pin, pout);
        k_cell1<<<NN / ROWS, 256>>>(pin, pout);
    }
    // after t=47: pout = 0 -> final h1 in buffer 0
    k_out<<<(NN * 12 + 255) / 256, 256>>>(outW, outb, out, 0);
}

// round 6
// speedup vs baseline: 1.0568x; 1.0568x over previous
#include <cuda_runtime.h>
#include <cuda_bf16.h>

#define NN   4096
#define TT   48
#define HH   64
#define C4   256
#define MAXW 128
#define ROWS 28
#define NTHR 448
#define GRID 147

typedef unsigned long long ull;

// ---------------- device scratch (no allocations allowed) ----------------
__device__ __align__(16) float g_dinv[NN];
__device__ __align__(16) int   g_cols[NN * MAXW];
__device__ __align__(16) float g_vals[NN * MAXW];
__device__ __align__(16) int   g_len[NN];
__device__ __align__(16) float g_AX[TT * NN * 2];
__device__ __align__(16) float g_W0[128 * C4];   // [gcWh0 ; liWh0]
__device__ __align__(16) float g_Wx0[4 * C4];    // [gcWi0 ; liWi0]
__device__ __align__(16) float g_b0[C4];
__device__ __align__(16) float g_W1[256 * C4];   // [gcWi1 ; liWi1 ; gcWh1 ; liWh1]
__device__ __align__(16) float g_b1[C4];
__device__ __align__(16) float g_h0[2][NN * HH];
__device__ __align__(16) float g_c0[2][NN * HH];
__device__ __align__(16) float g_h1[2][NN * HH];
__device__ __align__(16) float g_c1[2][NN * HH];

// ---------------- helpers ----------------
__device__ __forceinline__ ull pack2(float x, float y) {
    ull r; asm("mov.b64 %0,{%1,%2};" : "=l"(r) : "f"(x), "f"(y)); return r;
}
__device__ __forceinline__ void unpack2(ull v, float& x, float& y) {
    asm("mov.b64 {%0,%1},%2;" : "=f"(x), "=f"(y) : "l"(v));
}
// Blackwell packed dual-FMA (2x fp32 throughput); PTX-only form
__device__ __forceinline__ void fma2(ull& d, ull a, ull b) {
    asm("fma.rn.f32x2 %0,%1,%2,%0;" : "+l"(d) : "l"(a), "l"(b));
}
__device__ __forceinline__ float sigf(float v)  { return 1.f / (1.f + __expf(-v)); }
__device__ __forceinline__ float tanhf2(float v){ return 2.f / (1.f + __expf(-2.f * v)) - 1.f; }

// ---------------- setup kernels ----------------
__global__ void k_dinv(const float* __restrict__ adj) {
    int row  = blockIdx.x * 8 + (threadIdx.x >> 5);
    int lane = threadIdx.x & 31;
    if (row >= NN) return;
    float s = 0.f;
    for (int j = lane; j < NN; j += 32) s += adj[(size_t)row * NN + j];
    #pragma unroll
    for (int o = 16; o; o >>= 1) s += __shfl_xor_sync(0xffffffffu, s, o);
    if (lane == 0) g_dinv[row] = rsqrtf(s + 1.f);   // A = adj + I
}

__global__ void k_build(const float* __restrict__ adj) {
    int row  = blockIdx.x * 8 + (threadIdx.x >> 5);
    int lane = threadIdx.x & 31;
    if (row >= NN) return;
    float dr = g_dinv[row];
    int base = 0;
    for (int j0 = 0; j0 < NN; j0 += 32) {
        int   j    = j0 + lane;
        float v    = adj[(size_t)row * NN + j];
        bool  pres = (v != 0.f) || (j == row);
        float aval = v + ((j == row) ? 1.f : 0.f);
        unsigned m = __ballot_sync(0xffffffffu, pres);
        if (pres) {
            int pos = base + __popc(m & ((1u << lane) - 1u));
            if (pos < MAXW) {
                g_cols[row * MAXW + pos] = j;
                g_vals[row * MAXW + pos] = aval * dr * g_dinv[j];
            }
        }
        base += __popc(m);
    }
    if (base > MAXW) base = MAXW;
    if (lane == 0) g_len[row] = base;
}

__global__ void k_pack(const float* gcWi0, const float* gcWh0, const float* liWi0, const float* liWh0,
                       const float* gcWi1, const float* liWi1, const float* gcWh1, const float* liWh1,
                       const float* bi0, const float* bh0, const float* lbi0, const float* lbh0,
                       const float* bi1, const float* bh1, const float* lbi1, const float* lbh1) {
    int idx = blockIdx.x * blockDim.x + threadIdx.x;
    const int W0E = 128 * C4, W1E = 256 * C4, WXE = 4 * C4;
    if (idx < W0E) {
        int r = idx >> 8, c = idx & 255;
        g_W0[idx] = (r < 64) ? gcWh0[r * C4 + c] : liWh0[(r - 64) * C4 + c];
    } else if (idx < W0E + W1E) {
        int j = idx - W0E; int r = j >> 8, c = j & 255;
        int seg = r >> 6, rr = r & 63;
        const float* s = (seg == 0) ? gcWi1 : (seg == 1) ? liWi1 : (seg == 2) ? gcWh1 : liWh1;
        g_W1[j] = s[rr * C4 + c];
    } else if (idx < W0E + W1E + WXE) {
        int j = idx - W0E - W1E; int q = j >> 8, c = j & 255;
        g_Wx0[j] = (q < 2) ? gcWi0[q * C4 + c] : liWi0[(q - 2) * C4 + c];
    } else if (idx < W0E + W1E + WXE + C4) {
        int c = idx - (W0E + W1E + WXE);
        g_b0[c] = bi0[c] + bh0[c] + lbi0[c] + lbh0[c];
    } else if (idx < W0E + W1E + WXE + 2 * C4) {
        int c = idx - (W0E + W1E + WXE + C4);
        g_b1[c] = bi1[c] + bh1[c] + lbi1[c] + lbh1[c];
    }
}

__global__ void k_ax(const float* __restrict__ x) {
    int idx = blockIdx.x * blockDim.x + threadIdx.x;
    if (idx >= TT * NN) return;
    int t = idx / NN, i = idx - t * NN;
    int len = g_len[i];
    const int*   cp = g_cols + (size_t)i * MAXW;
    const float* vp = g_vals + (size_t)i * MAXW;
    float a0 = 0.f, a1 = 0.f;
    for (int k = 0; k < len; k++) {
        int c = cp[k]; float v = vp[k];
        float2 xv = *(const float2*)&x[(size_t)t * (NN * 2) + c * 2];
        a0 += v * xv.x; a1 += v * xv.y;
    }
    *(float2*)&g_AX[((size_t)t * NN + i) * 2] = make_float2(a0, a1);
}

__global__ void k_zero() {
    int idx = blockIdx.x * blockDim.x + threadIdx.x;
    if (idx < NN * HH) {
        g_h0[0][idx] = 0.f; g_c0[0][idx] = 0.f;
        g_h1[0][idx] = 0.f; g_c1[0][idx] = 0.f;
    }
}

// ================= cell 0: Ah0 gather + [Ah0|h0]@W0 + [AX|x]@Wx0 + gates =================
// dynamic smem: su[28][128] | sW[2][16][256] | sWx[4][256] | sx[28][4]
#define C0_SU   0
#define C0_SW   (ROWS * 128)
#define C0_SWX  (C0_SW + 2 * 16 * C4)
#define C0_SX   (C0_SWX + 4 * C4)
#define C0_SMEM ((C0_SX + ROWS * 4) * 4)

__global__ __launch_bounds__(NTHR) void k_cell0(const float* __restrict__ x, int t, int pin, int pout) {
    extern __shared__ __align__(16) float smem[];
    float (*su)[128]     = (float(*)[128])(smem + C0_SU);
    float (*sW)[16][C4]  = (float(*)[16][C4])(smem + C0_SW);
    float (*sWx)[C4]     = (float(*)[C4])(smem + C0_SWX);
    float (*sx)[4]       = (float(*)[4])(smem + C0_SX);

    const int tid  = threadIdx.x;
    const int row0 = blockIdx.x * ROWS;
    const float* __restrict__ h0o = g_h0[pin];

    // stage h0_old rows -> su[:,64:128)
    {
        int r = tid >> 4, q = tid & 15;
        int grow = min(row0 + r, NN - 1);
        *(float4*)&su[r][64 + q * 4] = *(const float4*)&h0o[(size_t)grow * HH + q * 4];
    }
    if (tid < 256) {                     // sWx (4x256)
        int kk = tid >> 6, q = tid & 63;
        *(float4*)&sWx[kk][q * 4] = *(const float4*)&g_Wx0[kk * C4 + q * 4];
    }
    if (tid < ROWS) {                    // x-term inputs
        int grow = min(row0 + tid, NN - 1);
        float2 axv = *(const float2*)&g_AX[((size_t)t * NN + grow) * 2];
        float2 xv  = *(const float2*)&x[(size_t)t * (NN * 2) + grow * 2];
        sx[tid][0] = axv.x; sx[tid][1] = axv.y;
        sx[tid][2] = xv.x;  sx[tid][3] = xv.y;
    }
    // prefetch W tile 0 into regs (latency hidden behind the gather)
    const float4* W4 = (const float4*)g_W0;
    float4 pf0 = W4[tid], pf1 = W4[tid + 448], pf2;
    if (tid < 128) pf2 = W4[tid + 896];

    // gather (A @ h0_old) -> su[:,0:64)
    {
        const int row = tid >> 4, lane = tid & 15;
        const int grow = min(row0 + row, NN - 1);
        const int len = g_len[grow];
        const int*   cb = g_cols + (size_t)grow * MAXW;
        const float* vb = g_vals + (size_t)grow * MAXW;
        float4 a4 = make_float4(0.f, 0.f, 0.f, 0.f);
        #pragma unroll 4
        for (int k = 0; k < len; k++) {
            int c = cb[k]; float v = vb[k];
            float4 hv = *(const float4*)&h0o[(size_t)c * HH + lane * 4];
            a4.x += v * hv.x; a4.y += v * hv.y; a4.z += v * hv.z; a4.w += v * hv.w;
        }
        *(float4*)&su[row][lane * 4] = a4;
    }
    // store W tile 0
    {
        float4* s4 = (float4*)sW[0];
        s4[tid] = pf0; s4[tid + 448] = pf1; if (tid < 128) s4[tid + 896] = pf2;
    }
    __syncthreads();

    // GEMM: [28 x 128] @ [128 x 256]; thread = 4 rows x 4 cols
    const int cg = tid & 63, rg = tid >> 6;      // rg 0..6
    const int c0 = cg * 4, r0 = rg * 4;
    ull acc[4][2];
    {
        float4 bb = *(const float4*)&g_b0[c0];
        ull b01 = pack2(bb.x, bb.y), b23 = pack2(bb.z, bb.w);
        #pragma unroll
        for (int r = 0; r < 4; r++) { acc[r][0] = b01; acc[r][1] = b23; }
        // x-term (K = 4)
        #pragma unroll
        for (int q = 0; q < 4; q++) {
            float4 wv = *(const float4*)&sWx[q][c0];
            ull w01 = pack2(wv.x, wv.y), w23 = pack2(wv.z, wv.w);
            #pragma unroll
            for (int r = 0; r < 4; r++) {
                float uv = sx[r0 + r][q];
                ull uu = pack2(uv, uv);
                fma2(acc[r][0], uu, w01); fma2(acc[r][1], uu, w23);
            }
        }
    }
    #pragma unroll 1
    for (int kt = 0; kt < 8; kt++) {
        if (kt < 7) {
            const float4* Wn = W4 + (size_t)(kt + 1) * 1024;
            pf0 = Wn[tid]; pf1 = Wn[tid + 448]; if (tid < 128) pf2 = Wn[tid + 896];
        }
        const float (*sWb)[C4] = sW[kt & 1];
        #pragma unroll
        for (int kk = 0; kk < 16; kk += 2) {
            float4 wa = *(const float4*)&sWb[kk][c0];
            float4 wb = *(const float4*)&sWb[kk + 1][c0];
            ull wa01 = pack2(wa.x, wa.y), wa23 = pack2(wa.z, wa.w);
            ull wb01 = pack2(wb.x, wb.y), wb23 = pack2(wb.z, wb.w);
            #pragma unroll
            for (int r = 0; r < 4; r++) {
                float2 uv = *(const float2*)&su[r0 + r][kt * 16 + kk];
                ull u0 = pack2(uv.x, uv.x), u1 = pack2(uv.y, uv.y);
                fma2(acc[r][0], u0, wa01); fma2(acc[r][1], u0, wa23);
                fma2(acc[r][0], u1, wb01); fma2(acc[r][1], u1, wb23);
            }
        }
        if (kt < 7) {
            float4* s4 = (float4*)sW[(kt + 1) & 1];
            s4[tid] = pf0; s4[tid + 448] = pf1; if (tid < 128) s4[tid + 896] = pf2;
        }
        __syncthreads();
    }

    // comb -> reuse sW storage as [28][256], then gates
    float* comb = (float*)sW;
    #pragma unroll
    for (int r = 0; r < 4; r++) {
        float a, b;
        unpack2(acc[r][0], a, b); *(float2*)&comb[(r0 + r) * C4 + c0]     = make_float2(a, b);
        unpack2(acc[r][1], a, b); *(float2*)&comb[(r0 + r) * C4 + c0 + 2] = make_float2(a, b);
    }
    __syncthreads();

    const float* __restrict__ cold = g_c0[pin];
    float* __restrict__ hn = g_h0[pout];
    float* __restrict__ cn = g_c0[pout];
    #pragma unroll
    for (int it = 0; it < 4; it++) {
        int i = tid + it * NTHR;             // 28*64 = 1792 = 4*448
        int r = i >> 6, h = i & 63;
        int grow = row0 + r;
        if (grow < NN) {
            float ig = comb[r * C4 + h],       fg = comb[r * C4 + 64 + h];
            float og = comb[r * C4 + 128 + h], gg = comb[r * C4 + 192 + h];
            size_t gi = (size_t)grow * HH + h;
            float cv = sigf(fg) * cold[gi] + sigf(ig) * tanhf2(gg);
            cn[gi] = cv;
            hn[gi] = sigf(og) * tanhf2(cv);
        }
    }
}

// ================= cell 1: gathers + [Ah0|h0|Ah1|h1]@W1 + gates =================
// dynamic smem: su[28][256] | sW[2][16][256]
#define C1_SU   0
#define C1_SW   (ROWS * C4)
#define C1_SMEM ((C1_SW + 2 * 16 * C4) * 4)

__global__ __launch_bounds__(NTHR) void k_cell1(int pin, int pout) {
    extern __shared__ __align__(16) float smem[];
    float (*su)[C4]     = (float(*)[C4])(smem + C1_SU);
    float (*sW)[16][C4] = (float(*)[16][C4])(smem + C1_SW);

    const int tid  = threadIdx.x;
    const int row0 = blockIdx.x * ROWS;
    const float* __restrict__ h0n = g_h0[pout];   // new h0 from cell0 this step
    const float* __restrict__ h1o = g_h1[pin];

    // stage h0n -> su[:,64:128), h1o -> su[:,192:256)
    {
        int r = tid >> 4, q = tid & 15;
        int grow = min(row0 + r, NN - 1);
        *(float4*)&su[r][64  + q * 4] = *(const float4*)&h0n[(size_t)grow * HH + q * 4];
        *(float4*)&su[r][192 + q * 4] = *(const float4*)&h1o[(size_t)grow * HH + q * 4];
    }
    // prefetch W tile 0
    const float4* W4 = (const float4*)g_W1;
    float4 pf0 = W4[tid], pf1 = W4[tid + 448], pf2;
    if (tid < 128) pf2 = W4[tid + 896];

    // gather A@h0n -> su[:,0:64), A@h1o -> su[:,128:192)
    {
        const int row = tid >> 4, lane = tid & 15;
        const int grow = min(row0 + row, NN - 1);
        const int len = g_len[grow];
        const int*   cb = g_cols + (size_t)grow * MAXW;
        const float* vb = g_vals + (size_t)grow * MAXW;
        float4 a0 = make_float4(0.f, 0.f, 0.f, 0.f);
        float4 a1 = make_float4(0.f, 0.f, 0.f, 0.f);
        #pragma unroll 2
        for (int k = 0; k < len; k++) {
            int c = cb[k]; float v = vb[k];
            float4 hv0 = *(const float4*)&h0n[(size_t)c * HH + lane * 4];
            float4 hv1 = *(const float4*)&h1o[(size_t)c * HH + lane * 4];
            a0.x += v * hv0.x; a0.y += v * hv0.y; a0.z += v * hv0.z; a0.w += v * hv0.w;
            a1.x += v * hv1.x; a1.y += v * hv1.y; a1.z += v * hv1.z; a1.w += v * hv1.w;
        }
        *(float4*)&su[row][lane * 4]       = a0;
        *(float4*)&su[row][128 + lane * 4] = a1;
    }
    {
        float4* s4 = (float4*)sW[0];
        s4[tid] = pf0; s4[tid + 448] = pf1; if (tid < 128) s4[tid + 896] = pf2;
    }
    __syncthreads();

    // GEMM: [28 x 256] @ [256 x 256]
    const int cg = tid & 63, rg = tid >> 6;
    const int c0 = cg * 4, r0 = rg * 4;
    ull acc[4][2];
    {
        float4 bb = *(const float4*)&g_b1[c0];
        ull b01 = pack2(bb.x, bb.y), b23 = pack2(bb.z, bb.w);
        #pragma unroll
        for (int r = 0; r < 4; r++) { acc[r][0] = b01; acc[r][1] = b23; }
    }
    #pragma unroll 1
    for (int kt = 0; kt < 16; kt++) {
        if (kt < 15) {
            const float4* Wn = W4 + (size_t)(kt + 1) * 1024;
            pf0 = Wn[tid]; pf1 = Wn[tid + 448]; if (tid < 128) pf2 = Wn[tid + 896];
        }
        const float (*sWb)[C4] = sW[kt & 1];
        #pragma unroll
        for (int kk = 0; kk < 16; kk += 2) {
            float4 wa = *(const float4*)&sWb[kk][c0];
            float4 wb = *(const float4*)&sWb[kk + 1][c0];
            ull wa01 = pack2(wa.x, wa.y), wa23 = pack2(wa.z, wa.w);
            ull wb01 = pack2(wb.x, wb.y), wb23 = pack2(wb.z, wb.w);
            #pragma unroll
            for (int r = 0; r < 4; r++) {
                float2 uv = *(const float2*)&su[r0 + r][kt * 16 + kk];
                ull u0 = pack2(uv.x, uv.x), u1 = pack2(uv.y, uv.y);
                fma2(acc[r][0], u0, wa01); fma2(acc[r][1], u0, wa23);
                fma2(acc[r][0], u1, wb01); fma2(acc[r][1], u1, wb23);
            }
        }
        if (kt < 15) {
            float4* s4 = (float4*)sW[(kt + 1) & 1];
            s4[tid] = pf0; s4[tid + 448] = pf1; if (tid < 128) s4[tid + 896] = pf2;
        }
        __syncthreads();
    }

    // comb -> reuse sW storage, then gates
    float* comb = (float*)sW;
    #pragma unroll
    for (int r = 0; r < 4; r++) {
        float a, b;
        unpack2(acc[r][0], a, b); *(float2*)&comb[(r0 + r) * C4 + c0]     = make_float2(a, b);
        unpack2(acc[r][1], a, b); *(float2*)&comb[(r0 + r) * C4 + c0 + 2] = make_float2(a, b);
    }
    __syncthreads();

    const float* __restrict__ cold = g_c1[pin];
    float* __restrict__ hn = g_h1[pout];
    float* __restrict__ cn = g_c1[pout];
    #pragma unroll
    for (int it = 0; it < 4; it++) {
        int i = tid + it * NTHR;
        int r = i >> 6, h = i & 63;
        int grow = row0 + r;
        if (grow < NN) {
            float ig = comb[r * C4 + h],       fg = comb[r * C4 + 64 + h];
            float og = comb[r * C4 + 128 + h], gg = comb[r * C4 + 192 + h];
            size_t gi = (size_t)grow * HH + h;
            float cv = sigf(fg) * cold[gi] + sigf(ig) * tanhf2(gg);
            cn[gi] = cv;
            hn[gi] = sigf(og) * tanhf2(cv);
        }
    }
}

// ---------------- output projection: h1 @ outW + outb ----------------
__global__ void k_out(const float* __restrict__ outW, const float* __restrict__ outb,
                      float* __restrict__ out, int hbuf) {
    int idx = blockIdx.x * blockDim.x + threadIdx.x;
    if (idx >= NN * 12) return;
    int n = idx / 12, p = idx - n * 12;
    const float* h = g_h1[hbuf] + (size_t)n * HH;
    float s = outb[p];
    #pragma unroll
    for (int k = 0; k < HH; k++) s += h[k] * outW[k * 12 + p];
    out[idx] = s;
}

extern "C" void kernel_launch(void* const* d_in, const int* in_sizes, int n_in,
                              void* d_out, int out_size) {
    const float* x     = (const float*)d_in[0];
    const float* adj   = (const float*)d_in[1];
    const float* gcWi0 = (const float*)d_in[2];
    const float* gcbi0 = (const float*)d_in[3];
    const float* gcWh0 = (const float*)d_in[4];
    const float* gcbh0 = (const float*)d_in[5];
    const float* liWi0 = (const float*)d_in[6];
    const float* libi0 = (const float*)d_in[7];
    const float* liWh0 = (const float*)d_in[8];
    const float* libh0 = (const float*)d_in[9];
    const float* gcWi1 = (const float*)d_in[10];
    const float* gcbi1 = (const float*)d_in[11];
    const float* gcWh1 = (const float*)d_in[12];
    const float* gcbh1 = (const float*)d_in[13];
    const float* liWi1 = (const float*)d_in[14];
    const float* libi1 = (const float*)d_in[15];
    const float* liWh1 = (const float*)d_in[16];
    const float* libh1 = (const float*)d_in[17];
    const float* outW  = (const float*)d_in[18];
    const float* outb  = (const float*)d_in[19];
    float* out = (float*)d_out;

    cudaFuncSetAttribute(k_cell0, cudaFuncAttributeMaxDynamicSharedMemorySize, C0_SMEM);
    cudaFuncSetAttribute(k_cell1, cudaFuncAttributeMaxDynamicSharedMemorySize, C1_SMEM);

    k_dinv<<<NN / 8, 256>>>(adj);
    k_build<<<NN / 8, 256>>>(adj);
    k_pack<<<(128 * C4 + 256 * C4 + 4 * C4 + 2 * C4 + 255) / 256, 256>>>(
        gcWi0, gcWh0, liWi0, liWh0, gcWi1, liWi1, gcWh1, liWh1,
        gcbi0, gcbh0, libi0, libh0, gcbi1, gcbh1, libi1, libh1);
    k_zero<<<(NN * HH + 255) / 256, 256>>>();
    k_ax<<<(TT * NN + 255) / 256, 256>>>(x);

    for (int t = 0; t < TT; t++) {
        int pin = t & 1, pout = pin ^ 1;
        k_cell0<<<GRID, NTHR, C0_SMEM>>>(x, t, pin, pout);
        k_cell1<<<GRID, NTHR, C1_SMEM>>>(pin, pout);
    }
    // after t=47: pout = 0 -> final h1 in buffer 0
    k_out<<<(NN * 12 + 255) / 256, 256>>>(outW, outb, out, 0);
}